// round 4
// baseline (speedup 1.0000x reference)
#include <cuda_runtime.h>
#include <cuda_bf16.h>

// y[n] = beta_0 + sum_{i<7,j<64} x[n,i,j] * w[i,j],  w = gamma^T @ alpha (rank 64)
// x: [131072, 7, 64] fp32. HBM-bound: 235 MB read -> ~34us floor.
// Single fused persistent kernel: each block computes w (448 floats) into smem,
// then grid-strides over row-pairs. 2 rows/warp = 224 float4 = 7 full warp loads.

#define N_GAMMA 7
#define N_ALPHA 64
#define RANK    64
#define W_ELEMS (N_GAMMA * N_ALPHA)   // 448
#define W_F4    (W_ELEMS / 4)         // 112
#define WARPS_PER_BLOCK 8
#define GRID_BLOCKS 912               // 152 SMs * 6 resident blocks

__device__ __forceinline__ float fma4(float acc, float4 v, float4 w) {
    acc = fmaf(v.x, w.x, acc);
    acc = fmaf(v.y, w.y, acc);
    acc = fmaf(v.z, w.z, acc);
    acc = fmaf(v.w, w.w, acc);
    return acc;
}

__global__ __launch_bounds__(256, 6) void cp_fused_kernel(
    const float* __restrict__ x,
    const float* __restrict__ beta0_p,
    const float* __restrict__ gamma,   // [64,7]
    const float* __restrict__ alpha,   // [64,64]
    float* __restrict__ y,
    int n_rows)
{
    __shared__ float4 sw[W_F4];

    // --- In-block w computation: thread t (< 112) computes w[4t..4t+3]. ---
    // idx = 4t -> i = t/16 (constant over the 4), j0 = (4t)%64, j0/4 = t%16.
    {
        int t = threadIdx.x;
        if (t < W_F4) {
            int i0 = t >> 4;       // gamma column, 0..6
            int jc = t & 15;       // alpha float4 column, 0..15
            const float4* a4 = reinterpret_cast<const float4*>(alpha);
            float4 s = make_float4(0.f, 0.f, 0.f, 0.f);
#pragma unroll
            for (int r = 0; r < RANK; r++) {
                float g = gamma[r * N_GAMMA + i0];
                float4 av = a4[r * (N_ALPHA / 4) + jc];
                s.x = fmaf(g, av.x, s.x);
                s.y = fmaf(g, av.y, s.y);
                s.z = fmaf(g, av.z, s.z);
                s.w = fmaf(g, av.w, s.w);
            }
            sw[t] = s;
        }
    }
    __syncthreads();

    int warp = threadIdx.x >> 5;
    int lane = threadIdx.x & 31;
    int warp_global = blockIdx.x * WARPS_PER_BLOCK + warp;
    int total_warps = gridDim.x * WARPS_PER_BLOCK;

    float beta0 = beta0_p[0];
    int n_pairs = (n_rows + 1) >> 1;

    // Precompute loop-invariant w reads.
    float4 w0 = sw[lane];
    float4 w1 = sw[lane + 32];
    float4 w2 = sw[lane + 64];
    float4 w3 = sw[(lane < 16) ? (lane + 96) : (lane - 16)];
    float4 w4 = sw[lane + 16];
    float4 w5 = sw[lane + 48];
    float4 w6 = sw[lane + 80];

    for (int p = warp_global; p < n_pairs; p += total_warps) {
        int n0 = p * 2;
        const float4* xr = reinterpret_cast<const float4*>(x + (size_t)n0 * W_ELEMS);

        // 7 independent full-width 16B streaming loads (2 rows, perfectly coalesced).
        float4 v0 = __ldcs(xr + lane);
        float4 v1 = __ldcs(xr + lane + 32);
        float4 v2 = __ldcs(xr + lane + 64);
        float4 v3 = __ldcs(xr + lane + 96);
        float4 v4 = __ldcs(xr + lane + 128);
        float4 v5 = __ldcs(xr + lane + 160);
        float4 v6 = __ldcs(xr + lane + 192);

        float accA = 0.f, accB = 0.f;
        accA = fma4(accA, v0, w0);
        accA = fma4(accA, v1, w1);
        accA = fma4(accA, v2, w2);
        {   // t=3 straddles the row boundary: lanes 0-15 row A, lanes 16-31 row B.
            float d = fma4(0.f, v3, w3);
            if (lane < 16) accA += d; else accB += d;
        }
        accB = fma4(accB, v4, w4);
        accB = fma4(accB, v5, w5);
        accB = fma4(accB, v6, w6);

        // Two interleaved butterfly reductions.
#pragma unroll
        for (int o = 16; o > 0; o >>= 1) {
            accA += __shfl_xor_sync(0xFFFFFFFFu, accA, o);
            accB += __shfl_xor_sync(0xFFFFFFFFu, accB, o);
        }

        if (lane < 2 && n0 + lane < n_rows) {
            float r = (lane == 0) ? accA : accB;
            y[n0 + lane] = beta0 + r;
        }
    }
}

extern "C" void kernel_launch(void* const* d_in, const int* in_sizes, int n_in,
                              void* d_out, int out_size)
{
    const float* x     = (const float*)d_in[0];
    const float* beta0 = (const float*)d_in[1];
    const float* gamma = (const float*)d_in[2];
    const float* alpha = (const float*)d_in[3];
    float* y = (float*)d_out;

    int n_rows = in_sizes[0] / W_ELEMS;

    cp_fused_kernel<<<GRID_BLOCKS, 256>>>(x, beta0, gamma, alpha, y, n_rows);
}